// round 17
// baseline (speedup 1.0000x reference)
#include <cuda_runtime.h>
#include <cuda_bf16.h>
#include <mma.h>
#include <cstdint>
#include <cstddef>

using namespace nvcuda;

// Problem constants
#define N_NODES 50000
#define K_NB    32
#define D_IN    512
#define D_HID   128
#define D_OUT   64

#define M_PAD   50048   // 391 * 128

// Scratch (device globals: allocation-free, graph-capturable, zero-init)
__device__ float g_h [(size_t)M_PAD * D_HID];
__device__ float g_h1[(size_t)M_PAD * D_HID];
__device__ float g_g [(size_t)M_PAD * D_OUT];

// ---------------------------------------------------------------------------
// bf16-split helpers
// ---------------------------------------------------------------------------
__device__ __forceinline__ void split_bf16(float x, __nv_bfloat16& hi, __nv_bfloat16& lo) {
    hi = __float2bfloat16_rn(x);
    lo = __float2bfloat16_rn(x - __bfloat162float(hi));
}
__device__ __forceinline__ void store_split4(__nv_bfloat16* hi_base, __nv_bfloat16* lo_base,
                                             int off, float4 v) {
    __nv_bfloat16 h0,h1,h2,h3, l0,l1,l2,l3;
    split_bf16(v.x, h0, l0); split_bf16(v.y, h1, l1);
    split_bf16(v.z, h2, l2); split_bf16(v.w, h3, l3);
    *(__nv_bfloat162*)&hi_base[off]     = __nv_bfloat162(h0, h1);
    *(__nv_bfloat162*)&hi_base[off + 2] = __nv_bfloat162(h2, h3);
    *(__nv_bfloat162*)&lo_base[off]     = __nv_bfloat162(l0, l1);
    *(__nv_bfloat162*)&lo_base[off + 2] = __nv_bfloat162(l2, l3);
}

// ---------------------------------------------------------------------------
// bf16-split GEMM, DOUBLE-BUFFERED smem, ONE __syncthreads per k-tile.
// C[M,N] = A[M,K] @ B[K,N]; terms hi*hi + hi*lo + lo*hi.
// Block tile 128x64, 256 threads (8 warps, 4x2; 32x32/warp), BK=32,
// 2 CTAs/SM. Loads issued 2 tiles ahead; stores go to the idle buffer
// while MMAs read the live one.
// ---------------------------------------------------------------------------
#define GBK   32
#define GLDA  40                       // 32 + 8 pad (bf16 elems)
#define GLDB  72                       // 64 + 8 pad
#define GA_SZ (128 * GLDA)             // elems per A buffer
#define GB_SZ (GBK * GLDB)             // elems per B buffer
#define GSMEM_BYTES ((4 * GA_SZ + 4 * GB_SZ) * 2)   // 59392 B

template<int N_DIM, int K_DIM>
__global__ __launch_bounds__(256, 2)
void gemm_bf16s_db(const float* __restrict__ A, const float* __restrict__ B,
                   float* __restrict__ C, int M) {
    constexpr int T = K_DIM / GBK;

    extern __shared__ __nv_bfloat16 ds[];
    __nv_bfloat16* AsH[2] = { ds,             ds + GA_SZ };
    __nv_bfloat16* AsL[2] = { ds + 2 * GA_SZ, ds + 3 * GA_SZ };
    __nv_bfloat16* BsH[2] = { ds + 4 * GA_SZ,            ds + 4 * GA_SZ + GB_SZ };
    __nv_bfloat16* BsL[2] = { ds + 4 * GA_SZ + 2 * GB_SZ, ds + 4 * GA_SZ + 3 * GB_SZ };

    const int tid    = threadIdx.x;
    const int wid    = tid >> 5;
    const int warp_m = wid >> 1;            // 0..3 -> 32-row strip
    const int warp_n = wid & 1;             // 0..1 -> 32-col strip
    const int row0   = blockIdx.y * 128;
    const int col0   = blockIdx.x * 64;

    const int ar  = tid >> 3;               // A: rows ar + p*32, 8 thr/row
    const int ac4 = (tid & 7) * 4;
    const int br  = tid >> 4;               // B: rows br + p*16, 16 thr/row
    const int bc4 = (tid & 15) * 4;

    wmma::fragment<wmma::accumulator, 16, 16, 16, float> acc[2][2];
#pragma unroll
    for (int i = 0; i < 2; ++i)
#pragma unroll
        for (int j = 0; j < 2; ++j) wmma::fill_fragment(acc[i][j], 0.0f);

    float4 pa[4], pb[2];

    auto load_regs = [&](int t) {
        const int k0 = t * GBK;
#pragma unroll
        for (int p = 0; p < 4; ++p) {
            int row = ar + p * 32;
            pa[p] = make_float4(0.f, 0.f, 0.f, 0.f);
            if (row0 + row < M)
                pa[p] = *(const float4*)&A[(size_t)(row0 + row) * K_DIM + k0 + ac4];
        }
#pragma unroll
        for (int p = 0; p < 2; ++p)
            pb[p] = *(const float4*)&B[(size_t)(k0 + br + p * 16) * N_DIM + col0 + bc4];
    };
    auto store_smem = [&](int buf) {
#pragma unroll
        for (int p = 0; p < 4; ++p)
            store_split4(AsH[buf], AsL[buf], (ar + p * 32) * GLDA + ac4, pa[p]);
#pragma unroll
        for (int p = 0; p < 2; ++p)
            store_split4(BsH[buf], BsL[buf], (br + p * 16) * GLDB + bc4, pb[p]);
    };

    // Prologue: tile 0 in smem[0]; tile 1 loads in flight.
    load_regs(0);
    store_smem(0);
    if (T > 1) load_regs(1);
    __syncthreads();

    for (int t = 0; t < T; ++t) {
        const int buf = t & 1;
        // Compute tile t from smem[buf]
#pragma unroll
        for (int kk = 0; kk < 2; ++kk) {
            wmma::fragment<wmma::matrix_b, 16, 16, 16,
                           __nv_bfloat16, wmma::row_major> bh[2], bl[2];
#pragma unroll
            for (int j = 0; j < 2; ++j) {
                wmma::load_matrix_sync(bh[j], &BsH[buf][(kk * 16) * GLDB + warp_n * 32 + j * 16], GLDB);
                wmma::load_matrix_sync(bl[j], &BsL[buf][(kk * 16) * GLDB + warp_n * 32 + j * 16], GLDB);
            }
#pragma unroll
            for (int i = 0; i < 2; ++i) {
                wmma::fragment<wmma::matrix_a, 16, 16, 16,
                               __nv_bfloat16, wmma::row_major> ah, al;
                wmma::load_matrix_sync(ah, &AsH[buf][(warp_m * 32 + i * 16) * GLDA + kk * 16], GLDA);
                wmma::load_matrix_sync(al, &AsL[buf][(warp_m * 32 + i * 16) * GLDA + kk * 16], GLDA);
#pragma unroll
                for (int j = 0; j < 2; ++j) {
                    wmma::mma_sync(acc[i][j], ah, bh[j], acc[i][j]);
                    wmma::mma_sync(acc[i][j], ah, bl[j], acc[i][j]);
                    wmma::mma_sync(acc[i][j], al, bh[j], acc[i][j]);
                }
            }
        }
        // Stage tile t+1 into the idle buffer; start loads for t+2.
        if (t + 1 < T) {
            store_smem((t + 1) & 1);
            if (t + 2 < T) load_regs(t + 2);
        }
        __syncthreads();
    }

#pragma unroll
    for (int i = 0; i < 2; ++i)
#pragma unroll
        for (int j = 0; j < 2; ++j) {
            int r = row0 + warp_m * 32 + i * 16;
            int c = col0 + warp_n * 32 + j * 16;
            wmma::store_matrix_sync(&C[(size_t)r * N_DIM + c], acc[i][j],
                                    N_DIM, wmma::mem_row_major);
        }
}

// ---------------------------------------------------------------------------
// Batcher odd-even merge sort on float4 lanes, dual-pipe comparators.
// ---------------------------------------------------------------------------
template<int I, int J>
__device__ __forceinline__ void cmpswap4(float4* v) {
    constexpr bool USE_FMA = (((I * 37 + J * 11) % 19) < 6);
    if constexpr (USE_FMA) {
        float sx = v[I].x + v[J].x, dx = v[I].x - v[J].x;
        float sy = v[I].y + v[J].y, dy = v[I].y - v[J].y;
        float sz = v[I].z + v[J].z, dz = v[I].z - v[J].z;
        float sw = v[I].w + v[J].w, dw = v[I].w - v[J].w;
        float lx = (sx - fabsf(dx)) * 0.5f;
        float ly = (sy - fabsf(dy)) * 0.5f;
        float lz = (sz - fabsf(dz)) * 0.5f;
        float lw = (sw - fabsf(dw)) * 0.5f;
        v[I].x = lx; v[J].x = sx - lx;
        v[I].y = ly; v[J].y = sy - ly;
        v[I].z = lz; v[J].z = sz - lz;
        v[I].w = lw; v[J].w = sw - lw;
    } else {
        float ax = v[I].x, bx = v[J].x;
        float ay = v[I].y, by = v[J].y;
        float az = v[I].z, bz = v[J].z;
        float aw = v[I].w, bw = v[J].w;
        v[I].x = fminf(ax, bx); v[J].x = fmaxf(ax, bx);
        v[I].y = fminf(ay, by); v[J].y = fmaxf(ay, by);
        v[I].z = fminf(az, bz); v[J].z = fmaxf(az, bz);
        v[I].w = fminf(aw, bw); v[J].w = fmaxf(aw, bw);
    }
}

template<int I, int END, int STEP, int R>
__device__ __forceinline__ void oem_cloop(float4* v) {
    if constexpr (I + R < END) {
        cmpswap4<I, I + R>(v);
        oem_cloop<I + STEP, END, STEP, R>(v);
    }
}

template<int LO, int N, int R>
__device__ __forceinline__ void oem_merge(float4* v) {
    constexpr int M = R * 2;
    if constexpr (M < N) {
        oem_merge<LO, N, M>(v);
        oem_merge<LO + R, N, M>(v);
        oem_cloop<LO + R, LO + N, M, R>(v);
    } else {
        cmpswap4<LO, LO + R>(v);
    }
}

template<int LO, int N>
__device__ __forceinline__ void oem_sort(float4* v) {
    if constexpr (N > 1) {
        constexpr int M = N / 2;
        oem_sort<LO, M>(v);
        oem_sort<LO + M, M>(v);
        oem_merge<LO, N, 1>(v);
    }
}

__device__ __forceinline__ float4 median32_f4(float4* v) {
    oem_sort<0, 16>(v);
    oem_sort<0, 16>(v + 16);
    float mx = fminf(v[0].x, v[31].x);
    float my = fminf(v[0].y, v[31].y);
    float mz = fminf(v[0].z, v[31].z);
    float mw = fminf(v[0].w, v[31].w);
#pragma unroll
    for (int i = 1; i < 16; ++i) {
        mx = fmaxf(mx, fminf(v[i].x, v[31 - i].x));
        my = fmaxf(my, fminf(v[i].y, v[31 - i].y));
        mz = fmaxf(mz, fminf(v[i].z, v[31 - i].z));
        mw = fmaxf(mw, fminf(v[i].w, v[31 - i].w));
    }
    return make_float4(mx, my, mz, mw);
}

// ---------------------------------------------------------------------------
// Layer-1 median + bias + ReLU: 4 nodes/block, 32 threads/node, 4 feat/thread.
// ---------------------------------------------------------------------------
__global__ __launch_bounds__(128, 1)
void median_relu_f4(const int* __restrict__ nb, const float* __restrict__ bias) {
    const int local = threadIdx.x >> 5;
    const int n  = blockIdx.x * 4 + local;
    const int d4 = threadIdx.x & 31;

    __shared__ int sidx[4 * K_NB];
    if (threadIdx.x < 4 * K_NB)
        sidx[threadIdx.x] = nb[(size_t)(blockIdx.x * 4) * K_NB + threadIdx.x];
    __syncthreads();

    const float4* hp = (const float4*)g_h;
    float4 v[K_NB];
#pragma unroll
    for (int k = 0; k < K_NB; ++k)
        v[k] = __ldg(&hp[(size_t)sidx[local * K_NB + k] * (D_HID / 4) + d4]);

    float4 med = median32_f4(v);
    float4 b = ((const float4*)bias)[d4];
    float4 r = make_float4(fmaxf(med.x + b.x, 0.0f), fmaxf(med.y + b.y, 0.0f),
                           fmaxf(med.z + b.z, 0.0f), fmaxf(med.w + b.w, 0.0f));
    ((float4*)g_h1)[(size_t)n * (D_HID / 4) + d4] = r;
}

// ---------------------------------------------------------------------------
// Layer-2 median + bias: 8 nodes/block, 16 threads/node, 4 feat/thread.
// ---------------------------------------------------------------------------
__global__ __launch_bounds__(128, 1)
void median_f4_out(const int* __restrict__ nb, const float* __restrict__ bias,
                   float* __restrict__ out) {
    const int local = threadIdx.x >> 4;
    const int n  = blockIdx.x * 8 + local;
    const int d4 = threadIdx.x & 15;

    __shared__ int sidx[8 * K_NB];
    if (threadIdx.x < 128)
        sidx[threadIdx.x] = nb[(size_t)(blockIdx.x * 8) * K_NB + threadIdx.x];
    if (threadIdx.x < 8 * K_NB - 128)
        sidx[128 + threadIdx.x] = nb[(size_t)(blockIdx.x * 8) * K_NB + 128 + threadIdx.x];
    __syncthreads();

    const float4* gp = (const float4*)g_g;
    float4 v[K_NB];
#pragma unroll
    for (int k = 0; k < K_NB; ++k)
        v[k] = __ldg(&gp[(size_t)sidx[local * K_NB + k] * (D_OUT / 4) + d4]);

    float4 med = median32_f4(v);
    float4 b = ((const float4*)bias)[d4];
    ((float4*)out)[(size_t)n * (D_OUT / 4) + d4] =
        make_float4(med.x + b.x, med.y + b.y, med.z + b.z, med.w + b.w);
}

// ---------------------------------------------------------------------------
extern "C" void kernel_launch(void* const* d_in, const int* in_sizes, int n_in,
                              void* d_out, int out_size) {
    const float* feat = (const float*)d_in[0];
    const float* W1   = (const float*)d_in[1];
    const float* b1   = (const float*)d_in[2];
    const float* W2   = (const float*)d_in[3];
    const float* b2   = (const float*)d_in[4];
    const int*   nb   = (const int*)d_in[5];
    float* out = (float*)d_out;

    void *ph = nullptr, *ph1 = nullptr, *pg = nullptr;
    cudaGetSymbolAddress(&ph,  g_h);
    cudaGetSymbolAddress(&ph1, g_h1);
    cudaGetSymbolAddress(&pg,  g_g);
    float* h  = (float*)ph;
    float* h1 = (float*)ph1;
    float* g  = (float*)pg;

    static bool attr_done = false;
    if (!attr_done) {
        cudaFuncSetAttribute(gemm_bf16s_db<D_HID, D_IN>,
                             cudaFuncAttributeMaxDynamicSharedMemorySize, GSMEM_BYTES);
        cudaFuncSetAttribute(gemm_bf16s_db<D_OUT, D_HID>,
                             cudaFuncAttributeMaxDynamicSharedMemorySize, GSMEM_BYTES);
        attr_done = true;
    }

    // 1) h = feat @ W1   [50000,512]x[512,128]  (wmma bf16-split, dbl-buffered)
    {
        dim3 grid(D_HID / 64, M_PAD / 128);   // (2, 391)
        gemm_bf16s_db<D_HID, D_IN><<<grid, 256, GSMEM_BYTES>>>(feat, W1, h, N_NODES);
    }

    // 2) h1 = relu(median_k h[nb] + b1)
    median_relu_f4<<<N_NODES / 4, 128>>>(nb, b1);

    // 3) g = h1 @ W2   [50048,128]x[128,64]  (pad rows are 0)
    {
        dim3 grid(D_OUT / 64, M_PAD / 128);   // (1, 391)
        gemm_bf16s_db<D_OUT, D_HID><<<grid, 256, GSMEM_BYTES>>>(h1, W2, g, M_PAD);
    }

    // 4) out = median_k g[nb] + b2
    median_f4_out<<<N_NODES / 8, 128>>>(nb, b2, out);
}